// round 12
// baseline (speedup 1.0000x reference)
#include <cuda_runtime.h>
#include <math.h>

#define H 1024
#define S 32768
#define NBLOCK 592                       // 4-6 CTAs/SM; all resident even at 64 regs
#define NTHREAD 256
#define NWARP 8
#define GWARPS (NBLOCK * NWARP)          // 4736 warps
#define NF4 (S / 4)                      // 8192 output float4s

// Scratch (no allocations allowed in kernel_launch)
__device__ __align__(16) float g_vpart[4 * H];   // 4 d-quarter partials of v
__device__ __align__(16) float g_scores[S];
__device__ __align__(16) float g_pmax[NBLOCK];
__device__ __align__(16) float g_psum[NBLOCK];

// Grid barrier: counters self-reset, epoch flags monotonic -> graph-replay safe.
__device__ unsigned g_cnt[2];
__device__ unsigned g_flag[2];

__device__ __forceinline__ void grid_bar(int i) {
    __syncthreads();
    if (threadIdx.x == 0) {
        volatile unsigned* flag = &g_flag[i];
        unsigned snap = *flag;
        __threadfence();
        unsigned pos = atomicAdd(&g_cnt[i], 1u);
        if (pos == NBLOCK - 1) {
            g_cnt[i] = 0;
            __threadfence();
            atomicAdd(&g_flag[i], 1u);
        } else {
            while (*flag == snap) { __nanosleep(64); }
        }
        __threadfence();
    }
    __syncthreads();
}

__global__ __launch_bounds__(NTHREAD, 6)
void k_all(const float* __restrict__ hidden,
           const float* __restrict__ enc,
           const float* __restrict__ W,
           float* __restrict__ out) {
    __shared__ float  ph1[NWARP * 33];  // phase-1 partials (padded)
    __shared__ float4 sv[H / 4];        // v staged for scores (4 KB)
    __shared__ float  sm[NWARP], ss[NWARP];
    __shared__ float  sh[2];

    const int b    = blockIdx.x;
    const int t    = threadIdx.x;
    const int warp = t >> 5;
    const int lane = t & 31;

    // ---- Phase 1: W matvec partials over 128 blocks ---------------------------
    // block b<128: h-range (b&31)*32, d-quarter (b>>5)*256. 32 loads/thread.
    if (b < 128) {
        const int h0 = (b & 31) * 32;
        const int d0 = (b >> 5) * 256;
        float acc = 0.0f;
#pragma unroll 8
        for (int j = 0; j < 32; j++) {
            const int d = d0 + warp * 32 + j;
            acc = fmaf(__ldg(&hidden[d]), __ldg(&W[(size_t)d * H + h0 + lane]), acc);
        }
        ph1[warp * 33 + lane] = acc;
        __syncthreads();
        if (t < 32) {
            float v = 0.0f;
#pragma unroll
            for (int w = 0; w < NWARP; w++) v += ph1[w * 33 + t];
            g_vpart[(b >> 5) * H + h0 + t] = v;
        }
    }

    grid_bar(0);

    // ---- Phase 2 prologue: fold 4 partials while staging v into shared --------
    {
        const float4* vp = reinterpret_cast<const float4*>(g_vpart);
        float4 a = vp[t], c = vp[t + 256], d = vp[t + 512], e = vp[t + 768];
        sv[t] = make_float4(a.x + c.x + d.x + e.x, a.y + c.y + d.y + e.y,
                            a.z + c.z + d.z + e.z, a.w + c.w + d.w + e.w);
    }
    __syncthreads();

    // ---- Phase 2: scores, 1 row per warp-iteration, online stats --------------
    const int gwarp = b * NWARP + warp;
    float m = -INFINITY, s = 0.0f;

#pragma unroll 1
    for (int it = 0; it < 7; it++) {
        const int row = it * GWARPS + gwarp;
        if (row >= S) break;
        const float4* erow = reinterpret_cast<const float4*>(enc + (size_t)row * H);
        float a0 = 0.0f, a1 = 0.0f, a2 = 0.0f, a3 = 0.0f;   // 4 chains: short dep
#pragma unroll
        for (int i = 0; i < 8; i++) {
            const int idx = lane + 32 * i;
            float4 e = __ldg(&erow[idx]);
            float4 w = sv[idx];
            a0 = fmaf(e.x, w.x, a0);
            a1 = fmaf(e.y, w.y, a1);
            a2 = fmaf(e.z, w.z, a2);
            a3 = fmaf(e.w, w.w, a3);
        }
        float acc = (a0 + a1) + (a2 + a3);
#pragma unroll
        for (int off = 16; off > 0; off >>= 1)
            acc += __shfl_xor_sync(0xFFFFFFFFu, acc, off);
        if (lane == 0) g_scores[row] = acc;
        const float mn = fmaxf(m, acc);
        s = s * __expf(m - mn) + __expf(acc - mn);
        m = mn;
    }
    if (lane == 0) { sm[warp] = m; ss[warp] = s; }
    __syncthreads();

    if (warp == 0 && lane < NWARP) {
        float wm = sm[lane], wsum = ss[lane];
        float gm = wm;
#pragma unroll
        for (int off = 4; off > 0; off >>= 1)
            gm = fmaxf(gm, __shfl_xor_sync(0x000000FFu, gm, off));
        float e = wsum * __expf(wm - gm);
#pragma unroll
        for (int off = 4; off > 0; off >>= 1)
            e += __shfl_xor_sync(0x000000FFu, e, off);
        if (lane == 0) { g_pmax[b] = gm; g_psum[b] = e; }
    }

    grid_bar(1);

    // ---- Phase 3: redundant combine (592 pairs, two-pass loop) + normalize ----
    if (warp == 0) {
        float gm = -INFINITY;
        for (int idx = lane; idx < NBLOCK; idx += 32)
            gm = fmaxf(gm, g_pmax[idx]);
#pragma unroll
        for (int off = 16; off > 0; off >>= 1)
            gm = fmaxf(gm, __shfl_xor_sync(0xFFFFFFFFu, gm, off));
        float lsum = 0.0f;
        for (int idx = lane; idx < NBLOCK; idx += 32)
            lsum = fmaf(g_psum[idx], __expf(g_pmax[idx] - gm), lsum);
#pragma unroll
        for (int off = 16; off > 0; off >>= 1)
            lsum += __shfl_xor_sync(0xFFFFFFFFu, lsum, off);
        if (lane == 0) { sh[0] = gm; sh[1] = 1.0f / lsum; }
    }
    __syncthreads();
    const float gmax = sh[0], inv = sh[1];

    // contiguous per-block slice of the 8192 output float4s (~14 per block)
    const unsigned s0 = ((unsigned)b * NF4) / NBLOCK;
    const unsigned s1 = ((unsigned)(b + 1) * NF4) / NBLOCK;
    const unsigned i  = s0 + t;
    if (i < s1) {
        float4 sc = reinterpret_cast<const float4*>(g_scores)[i];
        float4 o;
        o.x = __expf(sc.x - gmax) * inv;
        o.y = __expf(sc.y - gmax) * inv;
        o.z = __expf(sc.z - gmax) * inv;
        o.w = __expf(sc.w - gmax) * inv;
        reinterpret_cast<float4*>(out)[i] = o;
    }
}

// ---------------------------------------------------------------------------
// Inputs: hidden[1024], encoder_outputs[32768*1024], W[1024*1024], b[1024]
// (b cancels in softmax). Output: float[32768].
// ---------------------------------------------------------------------------
extern "C" void kernel_launch(void* const* d_in, const int* in_sizes, int n_in,
                              void* d_out, int out_size) {
    const float* hidden = (const float*)d_in[0];
    const float* enc    = (const float*)d_in[1];
    const float* W      = (const float*)d_in[2];
    float* out          = (float*)d_out;

    k_all<<<NBLOCK, NTHREAD>>>(hidden, enc, W, out);
}

// round 13
// speedup vs baseline: 1.1658x; 1.1658x over previous
#include <cuda_runtime.h>
#include <math.h>

#define H 1024
#define S 32768
#define NBLOCK 888                       // 148 SMs x 6 CTAs — exactly resident
#define NTHREAD 256
#define NWARP 8
#define GWARPS (NBLOCK * NWARP)          // 7104 warps
#define NROWIT 5                         // ceil(32768 / 7104)
#define NF4 (S / 4)                      // 8192 output float4s

// Scratch (no allocations allowed in kernel_launch)
__device__ __align__(16) float g_vpart[4 * H];   // 4 d-quarter partials of v
__device__ __align__(16) float g_scores[S];
__device__ __align__(16) float g_pmax[NBLOCK];
__device__ __align__(16) float g_psum[NBLOCK];

// Grid barrier: counters self-reset, epoch flags monotonic -> graph-replay safe.
__device__ unsigned g_cnt[2];
__device__ unsigned g_flag[2];

__device__ __forceinline__ void grid_bar(int i) {
    __syncthreads();
    if (threadIdx.x == 0) {
        volatile unsigned* flag = &g_flag[i];
        unsigned snap = *flag;
        __threadfence();
        unsigned pos = atomicAdd(&g_cnt[i], 1u);
        if (pos == NBLOCK - 1) {
            g_cnt[i] = 0;
            __threadfence();
            atomicAdd(&g_flag[i], 1u);
        } else {
            while (*flag == snap) { __nanosleep(64); }
        }
        __threadfence();
    }
    __syncthreads();
}

__global__ __launch_bounds__(NTHREAD, 6)
void k_all(const float* __restrict__ hidden,
           const float* __restrict__ enc,
           const float* __restrict__ W,
           float* __restrict__ out) {
    __shared__ float  ph1[NWARP * 33];  // phase-1 partials (padded)
    __shared__ float4 sv[H / 4];        // v staged for scores (4 KB)
    __shared__ float  sm[NWARP], ss[NWARP];
    __shared__ float  sh[2];

    const int b    = blockIdx.x;
    const int t    = threadIdx.x;
    const int warp = t >> 5;
    const int lane = t & 31;

    // ---- Phase 1: W matvec partials over 128 blocks ---------------------------
    // block b<128: h-range (b&31)*32, d-quarter (b>>5)*256. 32 loads/thread.
    if (b < 128) {
        const int h0 = (b & 31) * 32;
        const int d0 = (b >> 5) * 256;
        float acc = 0.0f;
#pragma unroll 8
        for (int j = 0; j < 32; j++) {
            const int d = d0 + warp * 32 + j;
            acc = fmaf(__ldg(&hidden[d]), __ldg(&W[(size_t)d * H + h0 + lane]), acc);
        }
        ph1[warp * 33 + lane] = acc;
        __syncthreads();
        if (t < 32) {
            float v = 0.0f;
#pragma unroll
            for (int w = 0; w < NWARP; w++) v += ph1[w * 33 + t];
            g_vpart[(b >> 5) * H + h0 + t] = v;
        }
    }

    grid_bar(0);

    // ---- Phase 2 prologue: fold 4 partials while staging v into shared --------
    {
        const float4* vp = reinterpret_cast<const float4*>(g_vpart);
        float4 a = vp[t], c = vp[t + 256], d = vp[t + 512], e = vp[t + 768];
        sv[t] = make_float4(a.x + c.x + d.x + e.x, a.y + c.y + d.y + e.y,
                            a.z + c.z + d.z + e.z, a.w + c.w + d.w + e.w);
    }
    __syncthreads();

    // ---- Phase 2: scores, 1 row per warp-iteration, online stats --------------
    const int gwarp = b * NWARP + warp;
    float m = -INFINITY, s = 0.0f;

#pragma unroll 1
    for (int it = 0; it < NROWIT; it++) {
        const int row = it * GWARPS + gwarp;
        if (row >= S) break;
        const float4* erow = reinterpret_cast<const float4*>(enc + (size_t)row * H);
        float a0 = 0.0f, a1 = 0.0f, a2 = 0.0f, a3 = 0.0f;   // 4 chains: short dep
#pragma unroll
        for (int i = 0; i < 8; i++) {
            const int idx = lane + 32 * i;
            float4 e = __ldg(&erow[idx]);
            float4 w = sv[idx];
            a0 = fmaf(e.x, w.x, a0);
            a1 = fmaf(e.y, w.y, a1);
            a2 = fmaf(e.z, w.z, a2);
            a3 = fmaf(e.w, w.w, a3);
        }
        float acc = (a0 + a1) + (a2 + a3);
#pragma unroll
        for (int off = 16; off > 0; off >>= 1)
            acc += __shfl_xor_sync(0xFFFFFFFFu, acc, off);
        if (lane == 0) g_scores[row] = acc;
        const float mn = fmaxf(m, acc);
        s = s * __expf(m - mn) + __expf(acc - mn);
        m = mn;
    }
    if (lane == 0) { sm[warp] = m; ss[warp] = s; }
    __syncthreads();

    if (warp == 0 && lane < NWARP) {
        float wm = sm[lane], wsum = ss[lane];
        float gm = wm;
#pragma unroll
        for (int off = 4; off > 0; off >>= 1)
            gm = fmaxf(gm, __shfl_xor_sync(0x000000FFu, gm, off));
        float e = wsum * __expf(wm - gm);
#pragma unroll
        for (int off = 4; off > 0; off >>= 1)
            e += __shfl_xor_sync(0x000000FFu, e, off);
        if (lane == 0) { g_pmax[b] = gm; g_psum[b] = e; }
    }

    grid_bar(1);

    // ---- Phase 3: redundant combine (888 pairs, two-pass loop) + normalize ----
    if (warp == 0) {
        float gm = -INFINITY;
        for (int idx = lane; idx < NBLOCK; idx += 32)
            gm = fmaxf(gm, g_pmax[idx]);
#pragma unroll
        for (int off = 16; off > 0; off >>= 1)
            gm = fmaxf(gm, __shfl_xor_sync(0xFFFFFFFFu, gm, off));
        float lsum = 0.0f;
        for (int idx = lane; idx < NBLOCK; idx += 32)
            lsum = fmaf(g_psum[idx], __expf(g_pmax[idx] - gm), lsum);
#pragma unroll
        for (int off = 16; off > 0; off >>= 1)
            lsum += __shfl_xor_sync(0xFFFFFFFFu, lsum, off);
        if (lane == 0) { sh[0] = gm; sh[1] = 1.0f / lsum; }
    }
    __syncthreads();
    const float gmax = sh[0], inv = sh[1];

    // contiguous per-block slice of the 8192 output float4s (~9-10 per block)
    const unsigned s0 = ((unsigned)b * NF4) / NBLOCK;
    const unsigned s1 = ((unsigned)(b + 1) * NF4) / NBLOCK;
    const unsigned i  = s0 + t;
    if (i < s1) {
        float4 sc = reinterpret_cast<const float4*>(g_scores)[i];
        float4 o;
        o.x = __expf(sc.x - gmax) * inv;
        o.y = __expf(sc.y - gmax) * inv;
        o.z = __expf(sc.z - gmax) * inv;
        o.w = __expf(sc.w - gmax) * inv;
        reinterpret_cast<float4*>(out)[i] = o;
    }
}

// ---------------------------------------------------------------------------
// Inputs: hidden[1024], encoder_outputs[32768*1024], W[1024*1024], b[1024]
// (b cancels in softmax). Output: float[32768].
// ---------------------------------------------------------------------------
extern "C" void kernel_launch(void* const* d_in, const int* in_sizes, int n_in,
                              void* d_out, int out_size) {
    const float* hidden = (const float*)d_in[0];
    const float* enc    = (const float*)d_in[1];
    const float* W      = (const float*)d_in[2];
    float* out          = (float*)d_out;

    k_all<<<NBLOCK, NTHREAD>>>(hidden, enc, W, out);
}